// round 5
// baseline (speedup 1.0000x reference)
#include <cuda_runtime.h>
#include <math.h>

#define N_ATOMS 21
#define DESC 210
#define D_PAD 256
#define M_ 64
#define T_ 8192
#define QCONST 0.22360679774997896f   /* sqrt(5)/10 */
#define INV_Q  4.47213595499957939f   /* 10/sqrt(5) */
#define COEF   (5.0f/300.0f)          /* 5/(3*sig^2), sig=10 */
#define STD_ 1.0f
#define C_   0.0f
#define N_TCHUNK 32                   /* pass B split-K chunks */

// ---------------- scratch (static device arrays; no allocation) -------------
__device__ float g_qx[M_ * DESC];              // q / dist per (m, pair)
__device__ float g_qxtT[D_PAD * T_];           // q * xs_train, transposed, zero-padded d
__device__ float g_JT[D_PAD * T_];             // Jx_alphas transposed, zero-padded d
__device__ float g_c1[M_ * T_];
__device__ float g_c2[M_ * T_];
__device__ float g_e3[M_ * T_];
__device__ float g_Gpart[N_TCHUNK * M_ * D_PAD];  // split-K partials of G
__device__ float g_S1[M_];
__device__ float g_EsRaw[M_];

// pair index d -> (i, j), i > j, numpy tril_indices(k=-1) order
__device__ __forceinline__ void pair_ij(int d, int& i, int& j) {
    i = (int)((1.0f + sqrtf(8.0f * (float)d + 1.0f)) * 0.5f);
    while (i * (i - 1) / 2 > d) --i;
    while ((i + 1) * i / 2 <= d) ++i;
    j = d - i * (i - 1) / 2;
}

// ---------------- kernel 0: descriptors -------------------------------------
__global__ void k_desc(const float* __restrict__ Rs) {
    int m = blockIdx.x;
    int tid = threadIdx.x;
    __shared__ float sR[N_ATOMS * 3];
    if (tid < N_ATOMS * 3) sR[tid] = Rs[m * N_ATOMS * 3 + tid];
    __syncthreads();
    if (tid < DESC) {
        int i, j;
        pair_ij(tid, i, j);
        float dx = sR[i * 3 + 0] - sR[j * 3 + 0];
        float dy = sR[i * 3 + 1] - sR[j * 3 + 1];
        float dz = sR[i * 3 + 2] - sR[j * 3 + 2];
        float dist = sqrtf(dx * dx + dy * dy + dz * dz);
        g_qx[m * DESC + tid] = QCONST / dist;
    }
}

// ---------------- kernel 1: transpose xs_train / J to [D_PAD, T] ------------
__global__ void k_transpose(const float* __restrict__ xs_train,
                            const float* __restrict__ J) {
    __shared__ float tA[32][33];
    __shared__ float tB[32][33];
    int t0 = blockIdx.x * 32;
    int d0 = blockIdx.y * 32;
    int tx = threadIdx.x;
#pragma unroll
    for (int k = 0; k < 4; k++) {
        int ty = threadIdx.y + k * 8;
        int t = t0 + ty;
        int d = d0 + tx;
        float a = 0.f, b = 0.f;
        if (d < DESC) {
            a = xs_train[t * DESC + d] * QCONST;
            b = J[t * DESC + d];
        }
        tA[ty][tx] = a;
        tB[ty][tx] = b;
    }
    __syncthreads();
#pragma unroll
    for (int k = 0; k < 4; k++) {
        int ty = threadIdx.y + k * 8;
        int d = d0 + ty;
        int t = t0 + tx;
        g_qxtT[d * T_ + t] = tA[tx][ty];
        g_JT[d * T_ + t] = tB[tx][ty];
    }
}

// ---------------- kernel 2: pass A — per-(m,t) coefficients ------------------
__global__ void __launch_bounds__(256) k_passA() {
    int t = blockIdx.x * 256 + threadIdx.x;
    int m0 = blockIdx.y * 16;
    __shared__ float qxs[DESC * 16];   // [d][mm]
    for (int idx = threadIdx.x; idx < DESC * 16; idx += 256) {
        int d = idx >> 4, mm = idx & 15;
        qxs[idx] = g_qx[(m0 + mm) * DESC + d];
    }
    __syncthreads();

    float accs[16], accd[16];
#pragma unroll
    for (int mm = 0; mm < 16; mm++) { accs[mm] = 0.f; accd[mm] = 0.f; }

    for (int d = 0; d < DESC; d++) {
        float xt = g_qxtT[d * T_ + t];
        float jv = g_JT[d * T_ + t];
        const float4* q4 = (const float4*)&qxs[d * 16];
#pragma unroll
        for (int g = 0; g < 4; g++) {
            float4 v = q4[g];
            float xd;
            xd = v.x - xt; accs[g*4+0] += xd*xd; accd[g*4+0] += xd*jv;
            xd = v.y - xt; accs[g*4+1] += xd*xd; accd[g*4+1] += xd*jv;
            xd = v.z - xt; accs[g*4+2] += xd*xd; accd[g*4+2] += xd*jv;
            xd = v.w - xt; accs[g*4+3] += xd*xd; accd[g*4+3] += xd*jv;
        }
    }
#pragma unroll
    for (int mm = 0; mm < 16; mm++) {
        int m = m0 + mm;
        float xdist = sqrtf(accs[mm]);
        float ex = COEF * expf(-xdist);
        float dot = accd[mm];
        float c1 = ex * dot;
        float c2 = ex * (1.f + xdist);
        g_c1[m * T_ + t] = c1;
        g_c2[m * T_ + t] = c2;
        g_e3[m * T_ + t] = c2 * dot;
    }
}

// ---------------- kernel 3: per-m reductions (S1, Es) ------------------------
__global__ void k_reduce() {
    int m = blockIdx.x;
    int tid = threadIdx.x;  // 256
    float s1 = 0.f, se = 0.f;
    for (int t = tid; t < T_; t += 256) {
        s1 += g_c1[m * T_ + t];
        se += g_e3[m * T_ + t];
    }
#pragma unroll
    for (int o = 16; o; o >>= 1) {
        s1 += __shfl_down_sync(0xffffffffu, s1, o);
        se += __shfl_down_sync(0xffffffffu, se, o);
    }
    __shared__ float sh1[8], sh2[8];
    if ((tid & 31) == 0) { sh1[tid >> 5] = s1; sh2[tid >> 5] = se; }
    __syncthreads();
    if (tid == 0) {
        float a = 0.f, b = 0.f;
#pragma unroll
        for (int k = 0; k < 8; k++) { a += sh1[k]; b += sh2[k]; }
        g_S1[m] = a;
        g_EsRaw[m] = b;
    }
}

// ---------------- kernel 4: pass B — G = c1@qxt + c2@J (split-K) -------------
#define TSTEP 16
__global__ void __launch_bounds__(256) k_passB() {
    int dtile = blockIdx.x;      // 0..3  (64 d's each, padded to 256)
    int tchunk = blockIdx.y;     // 0..31 (256 t's each)
    int d0 = dtile * 64;
    int tbase = tchunk * 256;
    __shared__ float c1s[TSTEP][64];
    __shared__ float c2s[TSTEP][64];
    __shared__ float xts[TSTEP][64];
    __shared__ float jts[TSTEP][64];
    int tid = threadIdx.x;
    int m0 = (tid & 15) * 4;
    int dl0 = (tid >> 4) * 4;

    float acc[4][4];
#pragma unroll
    for (int a = 0; a < 4; a++)
#pragma unroll
        for (int b = 0; b < 4; b++) acc[a][b] = 0.f;

    for (int ts = 0; ts < 256; ts += TSTEP) {
#pragma unroll
        for (int i = 0; i < 4; i++) {
            int lin = tid + i * 256;      // 0..1023 covers 64 rows x 16 tt
            int row = lin >> 4;
            int tt = lin & 15;
            int t = tbase + ts + tt;
            c1s[tt][row] = g_c1[row * T_ + t];
            c2s[tt][row] = g_c2[row * T_ + t];
            xts[tt][row] = g_qxtT[(d0 + row) * T_ + t];
            jts[tt][row] = g_JT[(d0 + row) * T_ + t];
        }
        __syncthreads();
#pragma unroll
        for (int tt = 0; tt < TSTEP; tt++) {
            float4 c1v = *(const float4*)&c1s[tt][m0];
            float4 c2v = *(const float4*)&c2s[tt][m0];
            float4 xv  = *(const float4*)&xts[tt][dl0];
            float4 jv  = *(const float4*)&jts[tt][dl0];
            float c1a[4] = {c1v.x, c1v.y, c1v.z, c1v.w};
            float c2a[4] = {c2v.x, c2v.y, c2v.z, c2v.w};
            float xa[4]  = {xv.x, xv.y, xv.z, xv.w};
            float ja[4]  = {jv.x, jv.y, jv.z, jv.w};
#pragma unroll
            for (int mi = 0; mi < 4; mi++)
#pragma unroll
                for (int di = 0; di < 4; di++)
                    acc[mi][di] += c1a[mi] * xa[di] + c2a[mi] * ja[di];
        }
        __syncthreads();
    }
    float* dst = &g_Gpart[tchunk * (M_ * D_PAD)];
#pragma unroll
    for (int mi = 0; mi < 4; mi++)
#pragma unroll
        for (int di = 0; di < 4; di++)
            dst[(m0 + mi) * D_PAD + d0 + dl0 + di] = acc[mi][di];
}

// ---------------- kernel 5: assemble forces + energies -----------------------
__global__ void k_final(const float* __restrict__ Rs, float* __restrict__ out) {
    int m = blockIdx.x;
    int tid = threadIdx.x;  // 256
    __shared__ float sR[N_ATOMS * 3];
    __shared__ float sF[N_ATOMS * 3];
    if (tid < N_ATOMS * 3) {
        sR[tid] = Rs[m * N_ATOMS * 3 + tid];
        sF[tid] = 0.f;
    }
    __syncthreads();
    if (tid < DESC) {
        // reduce split-K partials
        float G = 0.f;
#pragma unroll 8
        for (int ch = 0; ch < N_TCHUNK; ch++)
            G += g_Gpart[ch * (M_ * D_PAD) + m * D_PAD + tid];
        float qx = g_qx[m * DESC + tid];
        float fsx = (qx * g_S1[m] - G) * STD_;
        float invd = qx * INV_Q;                 // 1/dist
        float w = fsx * invd * invd * invd;      // fsx / dist^3
        int i, j;
        pair_ij(tid, i, j);
        float dx = sR[i * 3 + 0] - sR[j * 3 + 0];
        float dy = sR[i * 3 + 1] - sR[j * 3 + 1];
        float dz = sR[i * 3 + 2] - sR[j * 3 + 2];
        atomicAdd(&sF[i * 3 + 0],  w * dx);
        atomicAdd(&sF[i * 3 + 1],  w * dy);
        atomicAdd(&sF[i * 3 + 2],  w * dz);
        atomicAdd(&sF[j * 3 + 0], -w * dx);
        atomicAdd(&sF[j * 3 + 1], -w * dy);
        atomicAdd(&sF[j * 3 + 2], -w * dz);
    }
    __syncthreads();
    if (tid < N_ATOMS * 3)
        out[M_ + m * (N_ATOMS * 3) + tid] = sF[tid];
    if (tid == 0)
        out[m] = C_ + STD_ * g_EsRaw[m] / QCONST;
}

// ---------------- launch -----------------------------------------------------
extern "C" void kernel_launch(void* const* d_in, const int* in_sizes, int n_in,
                              void* d_out, int out_size) {
    const float* Rs       = (const float*)d_in[0];
    const float* xs_train = (const float*)d_in[1];
    const float* J        = (const float*)d_in[2];
    float* out = (float*)d_out;

    k_desc<<<M_, 256>>>(Rs);
    {
        dim3 tb(32, 8);
        dim3 tg(T_ / 32, D_PAD / 32);
        k_transpose<<<tg, tb>>>(xs_train, J);
    }
    {
        dim3 ga(T_ / 256, M_ / 16);
        k_passA<<<ga, 256>>>();
    }
    k_reduce<<<M_, 256>>>();
    {
        dim3 gb(4, N_TCHUNK);
        k_passB<<<gb, 256>>>();
    }
    k_final<<<M_, 256>>>(Rs, out);
}

// round 6
// speedup vs baseline: 1.4331x; 1.4331x over previous
#include <cuda_runtime.h>
#include <math.h>

#define N_ATOMS 21
#define DESC 210
#define D_PAD 256
#define M_ 64
#define T_ 8192
#define QCONST 0.22360679774997896f   /* sqrt(5)/10 */
#define INV_Q  4.47213595499957939f   /* 10/sqrt(5) */
#define COEF   (5.0f/300.0f)          /* 5/(3*sig^2), sig=10 */
#define STD_ 1.0f
#define C_   0.0f
#define N_TCHUNK 32                   /* pass B split-K chunks (t-chunks of 256) */

// ---------------- scratch (static device arrays; no allocation) -------------
__device__ float  g_qx[M_ * DESC];          // q / dist per (m, pair)
__device__ float2 g_XJ[D_PAD * T_];         // {q*xs_train, Jx_alphas} transposed, d-padded
__device__ float2 g_C[M_ * T_];             // {c1, c2} per (m, t)
__device__ float  g_Gpart[N_TCHUNK * M_ * D_PAD];  // split-K partials of G
__device__ float  g_S1part[N_TCHUNK * M_];  // partial sums of c1 over t
__device__ float  g_E3part[N_TCHUNK * M_];  // partial sums of c2*dot over t

// pair index d -> (i, j), i > j, numpy tril_indices(k=-1) order
__device__ __forceinline__ void pair_ij(int d, int& i, int& j) {
    i = (int)((1.0f + sqrtf(8.0f * (float)d + 1.0f)) * 0.5f);
    while (i * (i - 1) / 2 > d) --i;
    while ((i + 1) * i / 2 <= d) ++i;
    j = d - i * (i - 1) / 2;
}

// ---------------- kernel 0: descriptors + transpose (merged) -----------------
__global__ void k_pre(const float* __restrict__ Rs,
                      const float* __restrict__ xs_train,
                      const float* __restrict__ J) {
    if (blockIdx.y == D_PAD / 32) {
        // ---- descriptor part: one block per m ----
        int m = blockIdx.x;
        if (m >= M_) return;
        int tid = threadIdx.y * 32 + threadIdx.x;
        __shared__ float sR[N_ATOMS * 3];
        if (tid < N_ATOMS * 3) sR[tid] = Rs[m * N_ATOMS * 3 + tid];
        __syncthreads();
        if (tid < DESC) {
            int i, j;
            pair_ij(tid, i, j);
            float dx = sR[i * 3 + 0] - sR[j * 3 + 0];
            float dy = sR[i * 3 + 1] - sR[j * 3 + 1];
            float dz = sR[i * 3 + 2] - sR[j * 3 + 2];
            float dist = sqrtf(dx * dx + dy * dy + dz * dz);
            g_qx[m * DESC + tid] = QCONST / dist;
        }
        return;
    }
    // ---- transpose part: [T, DESC] -> float2 [D_PAD, T] ----
    __shared__ float tA[32][33];
    __shared__ float tB[32][33];
    int t0 = blockIdx.x * 32;
    int d0 = blockIdx.y * 32;
    int tx = threadIdx.x;
#pragma unroll
    for (int k = 0; k < 4; k++) {
        int ty = threadIdx.y + k * 8;
        int t = t0 + ty;
        int d = d0 + tx;
        float a = 0.f, b = 0.f;
        if (d < DESC) {
            a = xs_train[t * DESC + d] * QCONST;
            b = J[t * DESC + d];
        }
        tA[ty][tx] = a;
        tB[ty][tx] = b;
    }
    __syncthreads();
#pragma unroll
    for (int k = 0; k < 4; k++) {
        int ty = threadIdx.y + k * 8;
        int d = d0 + ty;
        int t = t0 + tx;
        g_XJ[d * T_ + t] = make_float2(tA[tx][ty], tB[tx][ty]);
    }
}

// ---------------- kernel 1: pass A — coefficients + partial reductions -------
#define ACH 10   /* d-chunk; 210 = 21 * 10 */
__global__ void __launch_bounds__(256) k_passA() {
    int t = blockIdx.x * 256 + threadIdx.x;
    int m0 = blockIdx.y * 16;
    __shared__ float qxs[DESC * 16];   // [d][mm]
    for (int idx = threadIdx.x; idx < DESC * 16; idx += 256) {
        int d = idx >> 4, mm = idx & 15;
        qxs[idx] = g_qx[(m0 + mm) * DESC + d];
    }
    __syncthreads();

    float accs[16], accd[16];
#pragma unroll
    for (int mm = 0; mm < 16; mm++) { accs[mm] = 0.f; accd[mm] = 0.f; }

    for (int dc = 0; dc < DESC; dc += ACH) {
        float2 xj[ACH];
#pragma unroll
        for (int k = 0; k < ACH; k++) xj[k] = g_XJ[(dc + k) * T_ + t];
#pragma unroll
        for (int k = 0; k < ACH; k++) {
            float xt = xj[k].x;
            float jv = xj[k].y;
            const float4* q4 = (const float4*)&qxs[(dc + k) * 16];
#pragma unroll
            for (int g = 0; g < 4; g++) {
                float4 v = q4[g];
                float xd;
                xd = v.x - xt; accs[g*4+0] += xd*xd; accd[g*4+0] += xd*jv;
                xd = v.y - xt; accs[g*4+1] += xd*xd; accd[g*4+1] += xd*jv;
                xd = v.z - xt; accs[g*4+2] += xd*xd; accd[g*4+2] += xd*jv;
                xd = v.w - xt; accs[g*4+3] += xd*xd; accd[g*4+3] += xd*jv;
            }
        }
    }

    float tc1[16], te3[16];
#pragma unroll
    for (int mm = 0; mm < 16; mm++) {
        int m = m0 + mm;
        float xdist = sqrtf(accs[mm]);
        float ex = COEF * expf(-xdist);
        float dot = accd[mm];
        float c1 = ex * dot;
        float c2 = ex * (1.f + xdist);
        g_C[m * T_ + t] = make_float2(c1, c2);
        tc1[mm] = c1;
        te3[mm] = c2 * dot;
    }

    // block-level partial sums of c1 and e3 for each of the 16 m's
    int lane = threadIdx.x & 31, wid = threadIdx.x >> 5;
    __shared__ float2 wred[8][16];
#pragma unroll
    for (int mm = 0; mm < 16; mm++) {
        float a = tc1[mm], b = te3[mm];
#pragma unroll
        for (int o = 16; o; o >>= 1) {
            a += __shfl_down_sync(0xffffffffu, a, o);
            b += __shfl_down_sync(0xffffffffu, b, o);
        }
        if (lane == 0) wred[wid][mm] = make_float2(a, b);
    }
    __syncthreads();
    if (threadIdx.x < 16) {
        float a = 0.f, b = 0.f;
#pragma unroll
        for (int w = 0; w < 8; w++) { a += wred[w][threadIdx.x].x; b += wred[w][threadIdx.x].y; }
        g_S1part[blockIdx.x * M_ + m0 + threadIdx.x] = a;
        g_E3part[blockIdx.x * M_ + m0 + threadIdx.x] = b;
    }
}

// ---------------- kernel 2: pass B — G = c1@qxt + c2@J (split-K) -------------
#define TSTEP 16
__global__ void __launch_bounds__(256) k_passB() {
    int d0 = blockIdx.x * 64;        // 4 d-tiles (padded region contributes 0)
    int tchunk = blockIdx.y;         // 32 t-chunks of 256
    int tbase = tchunk * 256;
    __shared__ float c1s[TSTEP * 64];
    __shared__ float c2s[TSTEP * 64];
    __shared__ float xts[TSTEP * 64];
    __shared__ float jts[TSTEP * 64];
    int tid = threadIdx.x;
    int m0  = (tid & 15) * 4;
    int dl0 = (tid >> 4) * 4;
    int ttL = tid & 15;
    int rowL = tid >> 4;             // 0..15, +16 per i

    float4 acc[4];
#pragma unroll
    for (int mi = 0; mi < 4; mi++) acc[mi] = make_float4(0.f, 0.f, 0.f, 0.f);

    float2 pc[4], px[4];
    // prefetch chunk 0
#pragma unroll
    for (int i = 0; i < 4; i++) {
        int row = rowL + i * 16;
        int t = tbase + ttL;
        pc[i] = g_C[row * T_ + t];
        px[i] = g_XJ[(d0 + row) * T_ + t];
    }

    for (int ts = 0; ts < 256; ts += TSTEP) {
        // store prefetched chunk (XOR-swizzled: phys row = row ^ (tt*4 & 63))
        int sw = (ttL * 4) & 63;
#pragma unroll
        for (int i = 0; i < 4; i++) {
            int row = (rowL + i * 16) ^ sw;
            c1s[ttL * 64 + row] = pc[i].x;
            c2s[ttL * 64 + row] = pc[i].y;
            xts[ttL * 64 + row] = px[i].x;
            jts[ttL * 64 + row] = px[i].y;
        }
        __syncthreads();
        // prefetch next chunk while computing
        if (ts + TSTEP < 256) {
#pragma unroll
            for (int i = 0; i < 4; i++) {
                int row = rowL + i * 16;
                int t = tbase + ts + TSTEP + ttL;
                pc[i] = g_C[row * T_ + t];
                px[i] = g_XJ[(d0 + row) * T_ + t];
            }
        }
#pragma unroll
        for (int tt = 0; tt < TSTEP; tt++) {
            int s = (tt * 4) & 63;
            float4 c1v = *(const float4*)&c1s[tt * 64 + (m0 ^ s)];
            float4 c2v = *(const float4*)&c2s[tt * 64 + (m0 ^ s)];
            float4 xv  = *(const float4*)&xts[tt * 64 + (dl0 ^ s)];
            float4 jv  = *(const float4*)&jts[tt * 64 + (dl0 ^ s)];
            float c1a[4] = {c1v.x, c1v.y, c1v.z, c1v.w};
            float c2a[4] = {c2v.x, c2v.y, c2v.z, c2v.w};
#pragma unroll
            for (int mi = 0; mi < 4; mi++) {
                acc[mi].x += c1a[mi] * xv.x + c2a[mi] * jv.x;
                acc[mi].y += c1a[mi] * xv.y + c2a[mi] * jv.y;
                acc[mi].z += c1a[mi] * xv.z + c2a[mi] * jv.z;
                acc[mi].w += c1a[mi] * xv.w + c2a[mi] * jv.w;
            }
        }
        __syncthreads();
    }
    float* dst = &g_Gpart[tchunk * (M_ * D_PAD)];
#pragma unroll
    for (int mi = 0; mi < 4; mi++)
        *(float4*)&dst[(m0 + mi) * D_PAD + d0 + dl0] = acc[mi];
}

// ---------------- kernel 3: assemble forces + energies -----------------------
__global__ void k_final(const float* __restrict__ Rs, float* __restrict__ out) {
    int m = blockIdx.x;
    int tid = threadIdx.x;  // 256
    __shared__ float sR[N_ATOMS * 3];
    __shared__ float sF[N_ATOMS * 3];
    __shared__ float sS1, sEs;
    if (tid < N_ATOMS * 3) {
        sR[tid] = Rs[m * N_ATOMS * 3 + tid];
        sF[tid] = 0.f;
    }
    if (tid < 32) {
        float a = g_S1part[tid * M_ + m];
        float b = g_E3part[tid * M_ + m];
#pragma unroll
        for (int o = 16; o; o >>= 1) {
            a += __shfl_down_sync(0xffffffffu, a, o);
            b += __shfl_down_sync(0xffffffffu, b, o);
        }
        if (tid == 0) { sS1 = a; sEs = b; }
    }
    __syncthreads();
    if (tid < DESC) {
        float G = 0.f;
#pragma unroll 8
        for (int ch = 0; ch < N_TCHUNK; ch++)
            G += g_Gpart[ch * (M_ * D_PAD) + m * D_PAD + tid];
        float qx = g_qx[m * DESC + tid];
        float fsx = (qx * sS1 - G) * STD_;
        float invd = qx * INV_Q;                 // 1/dist
        float w = fsx * invd * invd * invd;      // fsx / dist^3
        int i, j;
        pair_ij(tid, i, j);
        float dx = sR[i * 3 + 0] - sR[j * 3 + 0];
        float dy = sR[i * 3 + 1] - sR[j * 3 + 1];
        float dz = sR[i * 3 + 2] - sR[j * 3 + 2];
        atomicAdd(&sF[i * 3 + 0],  w * dx);
        atomicAdd(&sF[i * 3 + 1],  w * dy);
        atomicAdd(&sF[i * 3 + 2],  w * dz);
        atomicAdd(&sF[j * 3 + 0], -w * dx);
        atomicAdd(&sF[j * 3 + 1], -w * dy);
        atomicAdd(&sF[j * 3 + 2], -w * dz);
    }
    __syncthreads();
    if (tid < N_ATOMS * 3)
        out[M_ + m * (N_ATOMS * 3) + tid] = sF[tid];
    if (tid == 0)
        out[m] = C_ + STD_ * sEs / QCONST;
}

// ---------------- launch -----------------------------------------------------
extern "C" void kernel_launch(void* const* d_in, const int* in_sizes, int n_in,
                              void* d_out, int out_size) {
    const float* Rs       = (const float*)d_in[0];
    const float* xs_train = (const float*)d_in[1];
    const float* J        = (const float*)d_in[2];
    float* out = (float*)d_out;

    {
        dim3 tb(32, 8);
        dim3 tg(T_ / 32, D_PAD / 32 + 1);   // extra y-row runs descriptor blocks
        k_pre<<<tg, tb>>>(Rs, xs_train, J);
    }
    {
        dim3 ga(T_ / 256, M_ / 16);
        k_passA<<<ga, 256>>>();
    }
    {
        dim3 gb(D_PAD / 64, N_TCHUNK);
        k_passB<<<gb, 256>>>();
    }
    k_final<<<M_, 256>>>(Rs, out);
}

// round 7
// speedup vs baseline: 1.4738x; 1.0284x over previous
#include <cuda_runtime.h>
#include <math.h>

#define N_ATOMS 21
#define DESC 210
#define D_PAD 256
#define M_ 64
#define T_ 8192
#define QCONST 0.22360679774997896f   /* sqrt(5)/10 */
#define INV_Q  4.47213595499957939f   /* 10/sqrt(5) */
#define COEF   (5.0f/300.0f)          /* 5/(3*sig^2), sig=10 */
#define STD_ 1.0f
#define C_   0.0f
#define N_TCHUNK 64                   /* pass B split-K chunks (t-chunks of 128) */
#define TCH 128                       /* t per pass-B chunk */

// ---------------- scratch (static device arrays; no allocation) -------------
__device__ float  g_qx[M_ * DESC];          // q / dist per (m, pair)
__device__ float  g_qnorm[M_];              // sum_d qx^2
__device__ float2 g_XJ[D_PAD * T_];         // {q*xs_train, Jx_alphas} transposed, d-padded
__device__ float2 g_C[M_ * T_];             // {c1, c2} per (m, t)
__device__ float  g_Gpart[N_TCHUNK * M_ * D_PAD];  // split-K partials of G
__device__ float  g_S1part[32 * M_];        // partial sums of c1 over t (per passA block col)
__device__ float  g_E3part[32 * M_];        // partial sums of c2*dot over t

// pair index d -> (i, j), i > j, numpy tril_indices(k=-1) order
__device__ __forceinline__ void pair_ij(int d, int& i, int& j) {
    i = (int)((1.0f + sqrtf(8.0f * (float)d + 1.0f)) * 0.5f);
    while (i * (i - 1) / 2 > d) --i;
    while ((i + 1) * i / 2 <= d) ++i;
    j = d - i * (i - 1) / 2;
}

// ---------------- kernel 0: descriptors + qnorm + transpose (merged) ---------
__global__ void k_pre(const float* __restrict__ Rs,
                      const float* __restrict__ xs_train,
                      const float* __restrict__ J) {
    if (blockIdx.y == D_PAD / 32) {
        // ---- descriptor part: one block per m ----
        int m = blockIdx.x;
        if (m >= M_) return;
        int tid = threadIdx.y * 32 + threadIdx.x;
        __shared__ float sR[N_ATOMS * 3];
        __shared__ float red[256];
        if (tid < N_ATOMS * 3) sR[tid] = Rs[m * N_ATOMS * 3 + tid];
        __syncthreads();
        float v = 0.f;
        if (tid < DESC) {
            int i, j;
            pair_ij(tid, i, j);
            float dx = sR[i * 3 + 0] - sR[j * 3 + 0];
            float dy = sR[i * 3 + 1] - sR[j * 3 + 1];
            float dz = sR[i * 3 + 2] - sR[j * 3 + 2];
            float dist = sqrtf(dx * dx + dy * dy + dz * dz);
            float qx = QCONST / dist;
            g_qx[m * DESC + tid] = qx;
            v = qx * qx;
        }
        red[tid] = v;
        __syncthreads();
#pragma unroll
        for (int s = 128; s; s >>= 1) {
            if (tid < s) red[tid] += red[tid + s];
            __syncthreads();
        }
        if (tid == 0) g_qnorm[m] = red[0];
        return;
    }
    // ---- transpose part: [T, DESC] -> float2 [D_PAD, T] ----
    __shared__ float tA[32][33];
    __shared__ float tB[32][33];
    int t0 = blockIdx.x * 32;
    int d0 = blockIdx.y * 32;
    int tx = threadIdx.x;
#pragma unroll
    for (int k = 0; k < 4; k++) {
        int ty = threadIdx.y + k * 8;
        int t = t0 + ty;
        int d = d0 + tx;
        float a = 0.f, b = 0.f;
        if (d < DESC) {
            a = xs_train[t * DESC + d] * QCONST;
            b = J[t * DESC + d];
        }
        tA[ty][tx] = a;
        tB[ty][tx] = b;
    }
    __syncthreads();
#pragma unroll
    for (int k = 0; k < 4; k++) {
        int ty = threadIdx.y + k * 8;
        int d = d0 + ty;
        int t = t0 + tx;
        g_XJ[d * T_ + t] = make_float2(tA[tx][ty], tB[tx][ty]);
    }
}

// ---------------- kernel 1: pass A — GEMM-form coefficients ------------------
#define ACH 10   /* d-chunk; 210 = 21 * 10 */
__global__ void __launch_bounds__(256) k_passA() {
    int t = blockIdx.x * 256 + threadIdx.x;
    int m0 = blockIdx.y * 16;
    __shared__ float qxs[DESC * 16];   // [d][mm]
    __shared__ float qn[16];
    if (threadIdx.x < 16) qn[threadIdx.x] = g_qnorm[m0 + threadIdx.x];
    for (int idx = threadIdx.x; idx < DESC * 16; idx += 256) {
        int d = idx >> 4, mm = idx & 15;
        qxs[idx] = g_qx[(m0 + mm) * DESC + d];
    }
    __syncthreads();

    float cross[16], qxj[16];
    float nt = 0.f, dJ = 0.f;
#pragma unroll
    for (int mm = 0; mm < 16; mm++) { cross[mm] = 0.f; qxj[mm] = 0.f; }

    for (int dc = 0; dc < DESC; dc += ACH) {
        float2 xj[ACH];
#pragma unroll
        for (int k = 0; k < ACH; k++) xj[k] = g_XJ[(dc + k) * T_ + t];
#pragma unroll
        for (int k = 0; k < ACH; k++) {
            float xt = xj[k].x;
            float jv = xj[k].y;
            nt += xt * xt;
            dJ += xt * jv;
            const float4* q4 = (const float4*)&qxs[(dc + k) * 16];
#pragma unroll
            for (int g = 0; g < 4; g++) {
                float4 v = q4[g];
                cross[g*4+0] += v.x * xt; qxj[g*4+0] += v.x * jv;
                cross[g*4+1] += v.y * xt; qxj[g*4+1] += v.y * jv;
                cross[g*4+2] += v.z * xt; qxj[g*4+2] += v.z * jv;
                cross[g*4+3] += v.w * xt; qxj[g*4+3] += v.w * jv;
            }
        }
    }

    float tc1[16], te3[16];
#pragma unroll
    for (int mm = 0; mm < 16; mm++) {
        int m = m0 + mm;
        float xd2 = fmaxf(qn[mm] + nt - 2.f * cross[mm], 0.f);
        float xdist = sqrtf(xd2);
        float ex = COEF * expf(-xdist);
        float dot = qxj[mm] - dJ;
        float c1 = ex * dot;
        float c2 = ex * (1.f + xdist);
        g_C[m * T_ + t] = make_float2(c1, c2);
        tc1[mm] = c1;
        te3[mm] = c2 * dot;
    }

    // block-level partial sums of c1 and e3 for each of the 16 m's
    int lane = threadIdx.x & 31, wid = threadIdx.x >> 5;
    __shared__ float2 wred[8][16];
#pragma unroll
    for (int mm = 0; mm < 16; mm++) {
        float a = tc1[mm], b = te3[mm];
#pragma unroll
        for (int o = 16; o; o >>= 1) {
            a += __shfl_down_sync(0xffffffffu, a, o);
            b += __shfl_down_sync(0xffffffffu, b, o);
        }
        if (lane == 0) wred[wid][mm] = make_float2(a, b);
    }
    __syncthreads();
    if (threadIdx.x < 16) {
        float a = 0.f, b = 0.f;
#pragma unroll
        for (int w = 0; w < 8; w++) { a += wred[w][threadIdx.x].x; b += wred[w][threadIdx.x].y; }
        g_S1part[blockIdx.x * M_ + m0 + threadIdx.x] = a;
        g_E3part[blockIdx.x * M_ + m0 + threadIdx.x] = b;
    }
}

// ---------------- kernel 2: pass B — G = c1@qxt + c2@J (split-K) -------------
#define TSTEP 16
__global__ void __launch_bounds__(256) k_passB() {
    int d0 = blockIdx.x * 64;        // 4 d-tiles (padded region contributes 0)
    int tchunk = blockIdx.y;         // 64 t-chunks of 128
    int tbase = tchunk * TCH;
    __shared__ float c1s[TSTEP * 64];
    __shared__ float c2s[TSTEP * 64];
    __shared__ float xts[TSTEP * 64];
    __shared__ float jts[TSTEP * 64];
    int tid = threadIdx.x;
    int m0  = (tid & 15) * 4;
    int dl0 = (tid >> 4) * 4;
    int ttL = tid & 15;
    int rowL = tid >> 4;             // 0..15, +16 per i

    float4 acc[4];
#pragma unroll
    for (int mi = 0; mi < 4; mi++) acc[mi] = make_float4(0.f, 0.f, 0.f, 0.f);

    float2 pc[4], px[4];
    // prefetch chunk 0
#pragma unroll
    for (int i = 0; i < 4; i++) {
        int row = rowL + i * 16;
        int t = tbase + ttL;
        pc[i] = g_C[row * T_ + t];
        px[i] = g_XJ[(d0 + row) * T_ + t];
    }

    for (int ts = 0; ts < TCH; ts += TSTEP) {
        // store prefetched chunk (XOR-swizzled: phys row = row ^ (tt*4 & 63))
        int sw = (ttL * 4) & 63;
#pragma unroll
        for (int i = 0; i < 4; i++) {
            int row = (rowL + i * 16) ^ sw;
            c1s[ttL * 64 + row] = pc[i].x;
            c2s[ttL * 64 + row] = pc[i].y;
            xts[ttL * 64 + row] = px[i].x;
            jts[ttL * 64 + row] = px[i].y;
        }
        __syncthreads();
        // prefetch next chunk while computing
        if (ts + TSTEP < TCH) {
#pragma unroll
            for (int i = 0; i < 4; i++) {
                int row = rowL + i * 16;
                int t = tbase + ts + TSTEP + ttL;
                pc[i] = g_C[row * T_ + t];
                px[i] = g_XJ[(d0 + row) * T_ + t];
            }
        }
#pragma unroll
        for (int tt = 0; tt < TSTEP; tt++) {
            int s = (tt * 4) & 63;
            float4 c1v = *(const float4*)&c1s[tt * 64 + (m0 ^ s)];
            float4 c2v = *(const float4*)&c2s[tt * 64 + (m0 ^ s)];
            float4 xv  = *(const float4*)&xts[tt * 64 + (dl0 ^ s)];
            float4 jv  = *(const float4*)&jts[tt * 64 + (dl0 ^ s)];
            float c1a[4] = {c1v.x, c1v.y, c1v.z, c1v.w};
            float c2a[4] = {c2v.x, c2v.y, c2v.z, c2v.w};
#pragma unroll
            for (int mi = 0; mi < 4; mi++) {
                acc[mi].x += c1a[mi] * xv.x + c2a[mi] * jv.x;
                acc[mi].y += c1a[mi] * xv.y + c2a[mi] * jv.y;
                acc[mi].z += c1a[mi] * xv.z + c2a[mi] * jv.z;
                acc[mi].w += c1a[mi] * xv.w + c2a[mi] * jv.w;
            }
        }
        __syncthreads();
    }
    float* dst = &g_Gpart[tchunk * (M_ * D_PAD)];
#pragma unroll
    for (int mi = 0; mi < 4; mi++)
        *(float4*)&dst[(m0 + mi) * D_PAD + d0 + dl0] = acc[mi];
}

// ---------------- kernel 3: assemble forces + energies -----------------------
__global__ void k_final(const float* __restrict__ Rs, float* __restrict__ out) {
    int m = blockIdx.x;
    int tid = threadIdx.x;  // 256
    __shared__ float sR[N_ATOMS * 3];
    __shared__ float sF[N_ATOMS * 3];
    __shared__ float sS1, sEs;
    if (tid < N_ATOMS * 3) {
        sR[tid] = Rs[m * N_ATOMS * 3 + tid];
        sF[tid] = 0.f;
    }
    if (tid < 32) {
        float a = g_S1part[tid * M_ + m];
        float b = g_E3part[tid * M_ + m];
#pragma unroll
        for (int o = 16; o; o >>= 1) {
            a += __shfl_down_sync(0xffffffffu, a, o);
            b += __shfl_down_sync(0xffffffffu, b, o);
        }
        if (tid == 0) { sS1 = a; sEs = b; }
    }
    __syncthreads();
    if (tid < DESC) {
        float G = 0.f;
#pragma unroll 8
        for (int ch = 0; ch < N_TCHUNK; ch++)
            G += g_Gpart[ch * (M_ * D_PAD) + m * D_PAD + tid];
        float qx = g_qx[m * DESC + tid];
        float fsx = (qx * sS1 - G) * STD_;
        float invd = qx * INV_Q;                 // 1/dist
        float w = fsx * invd * invd * invd;      // fsx / dist^3
        int i, j;
        pair_ij(tid, i, j);
        float dx = sR[i * 3 + 0] - sR[j * 3 + 0];
        float dy = sR[i * 3 + 1] - sR[j * 3 + 1];
        float dz = sR[i * 3 + 2] - sR[j * 3 + 2];
        atomicAdd(&sF[i * 3 + 0],  w * dx);
        atomicAdd(&sF[i * 3 + 1],  w * dy);
        atomicAdd(&sF[i * 3 + 2],  w * dz);
        atomicAdd(&sF[j * 3 + 0], -w * dx);
        atomicAdd(&sF[j * 3 + 1], -w * dy);
        atomicAdd(&sF[j * 3 + 2], -w * dz);
    }
    __syncthreads();
    if (tid < N_ATOMS * 3)
        out[M_ + m * (N_ATOMS * 3) + tid] = sF[tid];
    if (tid == 0)
        out[m] = C_ + STD_ * sEs / QCONST;
}

// ---------------- launch -----------------------------------------------------
extern "C" void kernel_launch(void* const* d_in, const int* in_sizes, int n_in,
                              void* d_out, int out_size) {
    const float* Rs       = (const float*)d_in[0];
    const float* xs_train = (const float*)d_in[1];
    const float* J        = (const float*)d_in[2];
    float* out = (float*)d_out;

    {
        dim3 tb(32, 8);
        dim3 tg(T_ / 32, D_PAD / 32 + 1);   // extra y-row runs descriptor blocks
        k_pre<<<tg, tb>>>(Rs, xs_train, J);
    }
    {
        dim3 ga(T_ / 256, M_ / 16);
        k_passA<<<ga, 256>>>();
    }
    {
        dim3 gb(D_PAD / 64, N_TCHUNK);
        k_passB<<<gb, 256>>>();
    }
    k_final<<<M_, 256>>>(Rs, out);
}